// round 9
// baseline (speedup 1.0000x reference)
#include <cuda_runtime.h>
#include <cuda_bf16.h>
#include <cstdint>

typedef unsigned long long ull;

#define BROWS 8192
#define NOUT  512
#define NKDIM 512
#define NCODE 512
#define GROUPS 4096
#define WDIM   64

#define KEFF  1536          // 3 precision segments * 512
#define GBM   64
#define GBN   128
#define GBK   32
#define KITERS (KEFF / GBK) // 48
#define ASTR  40            // padded bf16 row stride (conflict-free ldmatrix)

// ---------------- device scratch ----------------
__device__ __nv_bfloat16 g_A2[BROWS * KEFF];   // 25.2 MB
__device__ __nv_bfloat16 g_B2[NOUT * KEFF];    // 1.6 MB
__device__ int   g_idx[GROUPS];
__device__ float g_mind[GROUPS];

__device__ __forceinline__ uint32_t smem_u32(const void* p) {
    uint32_t a;
    asm("{ .reg .u64 t; cvta.to.shared.u64 t, %1; cvt.u32.u64 %0, t; }" : "=r"(a) : "l"(p));
    return a;
}
__device__ __forceinline__ void cp16(uint32_t dst, const void* src) {
    asm volatile("cp.async.cg.shared.global [%0], [%1], 16;" :: "r"(dst), "l"(src));
}
#define CP_COMMIT() asm volatile("cp.async.commit_group;" ::: "memory")
#define CP_WAIT0()  asm volatile("cp.async.wait_group 0;" ::: "memory")

__device__ __forceinline__ void ldm_x4(uint32_t addr, uint32_t& r0, uint32_t& r1,
                                       uint32_t& r2, uint32_t& r3) {
    asm volatile("ldmatrix.sync.aligned.m8n8.x4.shared.b16 {%0,%1,%2,%3}, [%4];"
                 : "=r"(r0), "=r"(r1), "=r"(r2), "=r"(r3) : "r"(addr));
}
__device__ __forceinline__ void mma_bf16(float* d, const uint32_t* a, const uint32_t* b) {
    asm volatile(
        "mma.sync.aligned.m16n8k16.row.col.f32.bf16.bf16.f32 "
        "{%0,%1,%2,%3}, {%4,%5,%6,%7}, {%8,%9}, {%0,%1,%2,%3};"
        : "+f"(d[0]), "+f"(d[1]), "+f"(d[2]), "+f"(d[3])
        : "r"(a[0]), "r"(a[1]), "r"(a[2]), "r"(a[3]), "r"(b[0]), "r"(b[1]));
}

// =====================================================================
// Kernel 1: FUSED  vq (blocks 0..255)  +  convert_a (blocks 256..4351).
// VQ math and convert_a math identical to verified R5/R7 kernels.
// =====================================================================
#define VQ_ROWS 16
#define VQ_BLOCKS (GROUPS / VQ_ROWS)   // 256
#define CA_BLOCKS (BROWS / 2)          // 4096 (2 rows / block @ 512 thr)

__global__ __launch_bounds__(512) void fused_vq_a(
    const float* __restrict__ weight, const float* __restrict__ embed,
    const float* __restrict__ x)
{
    if (blockIdx.x >= VQ_BLOCKS) {
        // ---------------- convert_a part ----------------
        const int b   = blockIdx.x - VQ_BLOCKS;
        const int tid = threadIdx.x;
        const int m   = b * 2 + (tid >> 8);
        const int k   = (tid & 255) * 2;

        const float2 v = *(const float2*)&x[m * NKDIM + k];
        __nv_bfloat162 hi = __float22bfloat162_rn(v);
        float2 res = make_float2(v.x - __bfloat162float(hi.x), v.y - __bfloat162float(hi.y));
        __nv_bfloat162 lo = __float22bfloat162_rn(res);

        __nv_bfloat16* row = g_A2 + (size_t)m * KEFF;
        *(__nv_bfloat162*)&row[k]        = hi;
        *(__nv_bfloat162*)&row[512 + k]  = lo;
        *(__nv_bfloat162*)&row[1024 + k] = hi;
        return;
    }

    // ---------------- vq part ----------------
    __shared__ float w_s[VQ_ROWS][WDIM];
    __shared__ float wn_s[VQ_ROWS];
    __shared__ float dist_s[VQ_ROWS][NCODE];

    const int tid = threadIdx.x;
    const int r0  = blockIdx.x * VQ_ROWS;

    for (int t = tid; t < VQ_ROWS * WDIM; t += 512)
        w_s[t / WDIM][t % WDIM] = weight[r0 * WDIM + t];
    __syncthreads();

    if (tid < VQ_ROWS) {
        float s = 0.f;
#pragma unroll
        for (int k = 0; k < WDIM; k++) { float v = w_s[tid][k]; s += v * v; }
        wn_s[tid] = s;
    }

    float acc[VQ_ROWS];
#pragma unroll
    for (int r = 0; r < VQ_ROWS; r++) acc[r] = 0.f;
    float en = 0.f;
    const int j = tid;
#pragma unroll 4
    for (int k = 0; k < WDIM; k++) {
        float e = embed[k * NCODE + j];
        en += e * e;
#pragma unroll
        for (int r = 0; r < VQ_ROWS; r++) acc[r] += w_s[r][k] * e;
    }
#pragma unroll
    for (int r = 0; r < VQ_ROWS; r++) dist_s[r][j] = en - 2.f * acc[r];
    __syncthreads();

    const int warp = tid >> 5, lane = tid & 31;
    float best = 3.4e38f; int bi = 0;
    for (int c = lane; c < NCODE; c += 32) {
        float v = dist_s[warp][c];
        if (v < best) { best = v; bi = c; }
    }
#pragma unroll
    for (int off = 16; off > 0; off >>= 1) {
        float ov = __shfl_down_sync(0xffffffffu, best, off);
        int   oi = __shfl_down_sync(0xffffffffu, bi,   off);
        if (ov < best) { best = ov; bi = oi; }
    }
    if (lane == 0) {
        g_idx[r0 + warp]  = bi;
        g_mind[r0 + warp] = wn_s[warp] + best;
    }
}

// =====================================================================
// Kernel 2: W_eff^T -> B2 bf16 [512 n][1536 k], segs [Bh | Bh | Bl].
// Block 0 folds the deterministic diff reduction. (verified R7)
// =====================================================================
__global__ __launch_bounds__(256) void convert_b(
    const float* __restrict__ embed, const float* __restrict__ weight,
    const int* __restrict__ use_qw_p, float* __restrict__ out, int out_size)
{
    const int n = blockIdx.x;          // 0..511
    const int k = threadIdx.x * 2;     // even k
    const int g = k >> 3, i0 = k & 7;
    const int og = n >> 3, om = n & 7;
    const int uq = use_qw_p ? *use_qw_p : 1;

    float v0, v1;
    if (uq) {
        const int ix = g_idx[g * 64 + og];
        v0 = embed[(i0 * 8 + om) * NCODE + ix];
        v1 = embed[((i0 + 1) * 8 + om) * NCODE + ix];
    } else {
        v0 = weight[(g * 64 + og) * WDIM + i0 * 8 + om];
        v1 = weight[(g * 64 + og) * WDIM + (i0 + 1) * 8 + om];
    }
    __nv_bfloat162 hi = __float22bfloat162_rn(make_float2(v0, v1));
    __nv_bfloat162 lo = __float22bfloat162_rn(
        make_float2(v0 - __bfloat162float(hi.x), v1 - __bfloat162float(hi.y)));

    __nv_bfloat16* row = g_B2 + (size_t)n * KEFF;
    *(__nv_bfloat162*)&row[k]        = hi;
    *(__nv_bfloat162*)&row[512 + k]  = hi;
    *(__nv_bfloat162*)&row[1024 + k] = lo;

    if (blockIdx.x == 0) {
        __shared__ float s[256];
        float a = 0.f;
        for (int i = threadIdx.x; i < GROUPS; i += 256) a += g_mind[i];
        s[threadIdx.x] = a;
        __syncthreads();
        for (int st = 128; st > 0; st >>= 1) {
            if (threadIdx.x < st) s[threadIdx.x] += s[threadIdx.x + st];
            __syncthreads();
        }
        if (threadIdx.x == 0 && out_size > BROWS * NOUT)
            out[BROWS * NOUT] = uq ? (s[0] / (float)(GROUPS * WDIM)) : 0.f;
    }
}

// =====================================================================
// Kernel 3: bf16 mma.sync GEMM. 64x128 CTA tile, 128 threads (2m x 2n
// warps, 32x64 warp tile — per-warp math identical to verified R5).
// BK=32, 2-stage static-smem cp.async pipeline, 30 KB smem -> 4 CTAs/SM.
// =====================================================================
__global__ __launch_bounds__(128, 4) void gemm_mma(float* __restrict__ C)
{
    __shared__ __nv_bfloat16 As[2][GBM][ASTR];  // 10 KB
    __shared__ __nv_bfloat16 Bs[2][GBN][ASTR];  // 20 KB

    const int tid  = threadIdx.x;
    const int lane = tid & 31;
    const int wid  = tid >> 5;
    const int wm   = wid & 1;    // 2 warps along M, 32 rows each
    const int wn   = wid >> 1;   // 2 warps along N, 64 cols each

    const int m0 = blockIdx.y * GBM;
    const int n0 = blockIdx.x * GBN;

    const __nv_bfloat16* Ag = g_A2 + (size_t)m0 * KEFF;
    const __nv_bfloat16* Bg = g_B2 + (size_t)n0 * KEFF;

    // A tile: 64 rows * 4 chunks = 256 chunks, 2/thread
    // B tile: 128 rows * 4 chunks = 512 chunks, 4/thread
    const int a_row0 = tid >> 2;          // chunks tid, tid+128
    const int seg    = tid & 3;
    const int a_row1 = a_row0 + 32;

    float acc[2][8][4];
#pragma unroll
    for (int mt = 0; mt < 2; mt++)
#pragma unroll
        for (int nt = 0; nt < 8; nt++)
#pragma unroll
            for (int q = 0; q < 4; q++) acc[mt][nt][q] = 0.f;

    auto load_stage = [&](int s, int kt) {
        cp16(smem_u32(&As[s][a_row0][seg * 8]), Ag + (size_t)a_row0 * KEFF + kt + seg * 8);
        cp16(smem_u32(&As[s][a_row1][seg * 8]), Ag + (size_t)a_row1 * KEFF + kt + seg * 8);
#pragma unroll
        for (int l = 0; l < 4; l++) {
            const int br = a_row0 + l * 32;
            cp16(smem_u32(&Bs[s][br][seg * 8]), Bg + (size_t)br * KEFF + kt + seg * 8);
        }
    };

    load_stage(0, 0);
    CP_COMMIT();

    for (int it = 0; it < KITERS; it++) {
        CP_WAIT0();
        __syncthreads();
        if (it + 1 < KITERS) {
            load_stage((it + 1) & 1, (it + 1) * GBK);
            CP_COMMIT();
        }
        const int s = it & 1;

        const uint32_t a_lane0 = smem_u32(&As[s][0][0]) +
            ((wm * 32 + (lane & 15)) * ASTR + (lane >> 4) * 8) * 2;
        const int bq = lane >> 3, br = lane & 7;
        const uint32_t b_lane0 = smem_u32(&Bs[s][0][0]) +
            ((wn * 64 + (bq >> 1) * 8 + br) * ASTR + (bq & 1) * 8) * 2;

#pragma unroll
        for (int ks = 0; ks < 2; ks++) {
            uint32_t a[2][4], b[8][2];
#pragma unroll
            for (int mt = 0; mt < 2; mt++)
                ldm_x4(a_lane0 + (mt * 16 * ASTR + ks * 16) * 2,
                       a[mt][0], a[mt][1], a[mt][2], a[mt][3]);
#pragma unroll
            for (int np = 0; np < 4; np++)
                ldm_x4(b_lane0 + (np * 16 * ASTR + ks * 16) * 2,
                       b[np * 2][0], b[np * 2][1], b[np * 2 + 1][0], b[np * 2 + 1][1]);
#pragma unroll
            for (int mt = 0; mt < 2; mt++)
#pragma unroll
                for (int nt = 0; nt < 8; nt++)
                    mma_bf16(acc[mt][nt], a[mt], b[nt]);
        }
    }

    // Epilogue (same per-warp fragment layout as R5)
#pragma unroll
    for (int mt = 0; mt < 2; mt++) {
        const int r0 = m0 + wm * 32 + mt * 16 + (lane >> 2);
#pragma unroll
        for (int nt = 0; nt < 8; nt++) {
            const int c = n0 + wn * 64 + nt * 8 + (lane & 3) * 2;
            *(float2*)&C[(size_t)r0 * NOUT + c]       = make_float2(acc[mt][nt][0], acc[mt][nt][1]);
            *(float2*)&C[(size_t)(r0 + 8) * NOUT + c] = make_float2(acc[mt][nt][2], acc[mt][nt][3]);
        }
    }
}

// =====================================================================
extern "C" void kernel_launch(void* const* d_in, const int* in_sizes, int n_in,
                              void* d_out, int out_size)
{
    const float* x      = (const float*)d_in[0];   // [8192, 512]
    const float* weight = (const float*)d_in[1];   // [64,64,8,8]
    const float* embed  = (const float*)d_in[2];   // [64,512]
    const int*   use_qw = (n_in >= 4) ? (const int*)d_in[3] : nullptr;
    float* out = (float*)d_out;

    fused_vq_a<<<VQ_BLOCKS + CA_BLOCKS, 512>>>(weight, embed, x);
    convert_b<<<NOUT, 256>>>(embed, weight, use_qw, out, out_size);
    gemm_mma<<<dim3(NOUT / GBN, BROWS / GBM), 128>>>(out);
}

// round 11
// speedup vs baseline: 1.0212x; 1.0212x over previous
#include <cuda_runtime.h>
#include <cuda_bf16.h>
#include <cstdint>

typedef unsigned long long ull;

#define BROWS 8192
#define NOUT  512
#define NKDIM 512
#define NCODE 512
#define GROUPS 4096
#define WDIM   64

#define KEFF  1536          // 3 precision segments * 512
#define GBM   64
#define GBN   128
#define GBK   32
#define KITERS (KEFF / GBK) // 48
#define ASTR  40            // padded bf16 row stride (conflict-free ldmatrix)

// ---------------- device scratch ----------------
__device__ __nv_bfloat16 g_A2[BROWS * KEFF];   // 25.2 MB
__device__ __nv_bfloat16 g_B2[NOUT * KEFF];    // 1.6 MB
__device__ int   g_idx[GROUPS];
__device__ float g_mind[GROUPS];

__device__ __forceinline__ uint32_t smem_u32(const void* p) {
    uint32_t a;
    asm("{ .reg .u64 t; cvta.to.shared.u64 t, %1; cvt.u32.u64 %0, t; }" : "=r"(a) : "l"(p));
    return a;
}
__device__ __forceinline__ void cp16(uint32_t dst, const void* src) {
    asm volatile("cp.async.cg.shared.global [%0], [%1], 16;" :: "r"(dst), "l"(src));
}
#define CP_COMMIT() asm volatile("cp.async.commit_group;" ::: "memory")
#define CP_WAIT0()  asm volatile("cp.async.wait_group 0;" ::: "memory")

__device__ __forceinline__ void ldm_x4(uint32_t addr, uint32_t& r0, uint32_t& r1,
                                       uint32_t& r2, uint32_t& r3) {
    asm volatile("ldmatrix.sync.aligned.m8n8.x4.shared.b16 {%0,%1,%2,%3}, [%4];"
                 : "=r"(r0), "=r"(r1), "=r"(r2), "=r"(r3) : "r"(addr));
}
__device__ __forceinline__ void mma_bf16(float* d, const uint32_t* a, const uint32_t* b) {
    asm volatile(
        "mma.sync.aligned.m16n8k16.row.col.f32.bf16.bf16.f32 "
        "{%0,%1,%2,%3}, {%4,%5,%6,%7}, {%8,%9}, {%0,%1,%2,%3};"
        : "+f"(d[0]), "+f"(d[1]), "+f"(d[2]), "+f"(d[3])
        : "r"(a[0]), "r"(a[1]), "r"(a[2]), "r"(a[3]), "r"(b[0]), "r"(b[1]));
}

// =====================================================================
// Kernel 1: VQ quantize (verified R5/R7, standalone again — 76 regs OK here)
// =====================================================================
#define VQ_ROWS 16

__global__ __launch_bounds__(512) void vq_kernel(
    const float* __restrict__ weight, const float* __restrict__ embed)
{
    __shared__ float w_s[VQ_ROWS][WDIM];
    __shared__ float wn_s[VQ_ROWS];
    __shared__ float dist_s[VQ_ROWS][NCODE];

    const int tid = threadIdx.x;
    const int r0  = blockIdx.x * VQ_ROWS;

    for (int t = tid; t < VQ_ROWS * WDIM; t += 512)
        w_s[t / WDIM][t % WDIM] = weight[r0 * WDIM + t];
    __syncthreads();

    if (tid < VQ_ROWS) {
        float s = 0.f;
#pragma unroll
        for (int k = 0; k < WDIM; k++) { float v = w_s[tid][k]; s += v * v; }
        wn_s[tid] = s;
    }

    float acc[VQ_ROWS];
#pragma unroll
    for (int r = 0; r < VQ_ROWS; r++) acc[r] = 0.f;
    float en = 0.f;
    const int j = tid;
#pragma unroll 4
    for (int k = 0; k < WDIM; k++) {
        float e = embed[k * NCODE + j];
        en += e * e;
#pragma unroll
        for (int r = 0; r < VQ_ROWS; r++) acc[r] += w_s[r][k] * e;
    }
#pragma unroll
    for (int r = 0; r < VQ_ROWS; r++) dist_s[r][j] = en - 2.f * acc[r];
    __syncthreads();

    const int warp = tid >> 5, lane = tid & 31;
    float best = 3.4e38f; int bi = 0;
    for (int c = lane; c < NCODE; c += 32) {
        float v = dist_s[warp][c];
        if (v < best) { best = v; bi = c; }
    }
#pragma unroll
    for (int off = 16; off > 0; off >>= 1) {
        float ov = __shfl_down_sync(0xffffffffu, best, off);
        int   oi = __shfl_down_sync(0xffffffffu, bi,   off);
        if (ov < best) { best = ov; bi = oi; }
    }
    if (lane == 0) {
        g_idx[r0 + warp]  = bi;
        g_mind[r0 + warp] = wn_s[warp] + best;
    }
}

// =====================================================================
// Kernel 2: x -> A2 bf16 [8192][1536], segments [Ah | Al | Ah]
// (verified R5/R7 standalone form — lightweight, high occupancy)
// =====================================================================
__global__ __launch_bounds__(256) void convert_a(const float* __restrict__ x)
{
    const int t = blockIdx.x * 256 + threadIdx.x;
    const int m = t >> 8;
    const int k = (t & 255) * 2;

    const float2 v = *(const float2*)&x[m * NKDIM + k];
    __nv_bfloat162 hi = __float22bfloat162_rn(v);
    float2 res = make_float2(v.x - __bfloat162float(hi.x), v.y - __bfloat162float(hi.y));
    __nv_bfloat162 lo = __float22bfloat162_rn(res);

    __nv_bfloat16* row = g_A2 + (size_t)m * KEFF;
    *(__nv_bfloat162*)&row[k]        = hi;
    *(__nv_bfloat162*)&row[512 + k]  = lo;
    *(__nv_bfloat162*)&row[1024 + k] = hi;
}

// =====================================================================
// Kernel 3: W_eff^T -> B2 bf16 [512 n][1536 k], segs [Bh | Bh | Bl].
// Block 0 folds the deterministic diff reduction. (verified R7)
// =====================================================================
__global__ __launch_bounds__(256) void convert_b(
    const float* __restrict__ embed, const float* __restrict__ weight,
    const int* __restrict__ use_qw_p, float* __restrict__ out, int out_size)
{
    const int n = blockIdx.x;          // 0..511
    const int k = threadIdx.x * 2;     // even k
    const int g = k >> 3, i0 = k & 7;
    const int og = n >> 3, om = n & 7;
    const int uq = use_qw_p ? *use_qw_p : 1;

    float v0, v1;
    if (uq) {
        const int ix = g_idx[g * 64 + og];
        v0 = embed[(i0 * 8 + om) * NCODE + ix];
        v1 = embed[((i0 + 1) * 8 + om) * NCODE + ix];
    } else {
        v0 = weight[(g * 64 + og) * WDIM + i0 * 8 + om];
        v1 = weight[(g * 64 + og) * WDIM + (i0 + 1) * 8 + om];
    }
    __nv_bfloat162 hi = __float22bfloat162_rn(make_float2(v0, v1));
    __nv_bfloat162 lo = __float22bfloat162_rn(
        make_float2(v0 - __bfloat162float(hi.x), v1 - __bfloat162float(hi.y)));

    __nv_bfloat16* row = g_B2 + (size_t)n * KEFF;
    *(__nv_bfloat162*)&row[k]        = hi;
    *(__nv_bfloat162*)&row[512 + k]  = hi;
    *(__nv_bfloat162*)&row[1024 + k] = lo;

    if (blockIdx.x == 0) {
        __shared__ float s[256];
        float a = 0.f;
        for (int i = threadIdx.x; i < GROUPS; i += 256) a += g_mind[i];
        s[threadIdx.x] = a;
        __syncthreads();
        for (int st = 128; st > 0; st >>= 1) {
            if (threadIdx.x < st) s[threadIdx.x] += s[threadIdx.x + st];
            __syncthreads();
        }
        if (threadIdx.x == 0 && out_size > BROWS * NOUT)
            out[BROWS * NOUT] = uq ? (s[0] / (float)(GROUPS * WDIM)) : 0.f;
    }
}

// =====================================================================
// Kernel 4: bf16 mma.sync GEMM. 64x128 CTA tile, 128 threads (2m x 2n
// warps, 32x64 warp tile), BK=32, 2-stage static-smem cp.async pipeline,
// 30 KB smem -> 4 CTAs/SM. (measured win in R8: ~39.5us vs 51.8)
// =====================================================================
__global__ __launch_bounds__(128, 4) void gemm_mma(float* __restrict__ C)
{
    __shared__ __nv_bfloat16 As[2][GBM][ASTR];  // 10 KB
    __shared__ __nv_bfloat16 Bs[2][GBN][ASTR];  // 20 KB

    const int tid  = threadIdx.x;
    const int lane = tid & 31;
    const int wid  = tid >> 5;
    const int wm   = wid & 1;    // 2 warps along M, 32 rows each
    const int wn   = wid >> 1;   // 2 warps along N, 64 cols each

    const int m0 = blockIdx.y * GBM;
    const int n0 = blockIdx.x * GBN;

    const __nv_bfloat16* Ag = g_A2 + (size_t)m0 * KEFF;
    const __nv_bfloat16* Bg = g_B2 + (size_t)n0 * KEFF;

    const int a_row0 = tid >> 2;
    const int seg    = tid & 3;
    const int a_row1 = a_row0 + 32;

    float acc[2][8][4];
#pragma unroll
    for (int mt = 0; mt < 2; mt++)
#pragma unroll
        for (int nt = 0; nt < 8; nt++)
#pragma unroll
            for (int q = 0; q < 4; q++) acc[mt][nt][q] = 0.f;

    auto load_stage = [&](int s, int kt) {
        cp16(smem_u32(&As[s][a_row0][seg * 8]), Ag + (size_t)a_row0 * KEFF + kt + seg * 8);
        cp16(smem_u32(&As[s][a_row1][seg * 8]), Ag + (size_t)a_row1 * KEFF + kt + seg * 8);
#pragma unroll
        for (int l = 0; l < 4; l++) {
            const int br = a_row0 + l * 32;
            cp16(smem_u32(&Bs[s][br][seg * 8]), Bg + (size_t)br * KEFF + kt + seg * 8);
        }
    };

    load_stage(0, 0);
    CP_COMMIT();

    for (int it = 0; it < KITERS; it++) {
        CP_WAIT0();
        __syncthreads();
        if (it + 1 < KITERS) {
            load_stage((it + 1) & 1, (it + 1) * GBK);
            CP_COMMIT();
        }
        const int s = it & 1;

        const uint32_t a_lane0 = smem_u32(&As[s][0][0]) +
            ((wm * 32 + (lane & 15)) * ASTR + (lane >> 4) * 8) * 2;
        const int bq = lane >> 3, br = lane & 7;
        const uint32_t b_lane0 = smem_u32(&Bs[s][0][0]) +
            ((wn * 64 + (bq >> 1) * 8 + br) * ASTR + (bq & 1) * 8) * 2;

#pragma unroll
        for (int ks = 0; ks < 2; ks++) {
            uint32_t a[2][4], b[8][2];
#pragma unroll
            for (int mt = 0; mt < 2; mt++)
                ldm_x4(a_lane0 + (mt * 16 * ASTR + ks * 16) * 2,
                       a[mt][0], a[mt][1], a[mt][2], a[mt][3]);
#pragma unroll
            for (int np = 0; np < 4; np++)
                ldm_x4(b_lane0 + (np * 16 * ASTR + ks * 16) * 2,
                       b[np * 2][0], b[np * 2][1], b[np * 2 + 1][0], b[np * 2 + 1][1]);
#pragma unroll
            for (int mt = 0; mt < 2; mt++)
#pragma unroll
                for (int nt = 0; nt < 8; nt++)
                    mma_bf16(acc[mt][nt], a[mt], b[nt]);
        }
    }

    // Epilogue
#pragma unroll
    for (int mt = 0; mt < 2; mt++) {
        const int r0 = m0 + wm * 32 + mt * 16 + (lane >> 2);
#pragma unroll
        for (int nt = 0; nt < 8; nt++) {
            const int c = n0 + wn * 64 + nt * 8 + (lane & 3) * 2;
            *(float2*)&C[(size_t)r0 * NOUT + c]       = make_float2(acc[mt][nt][0], acc[mt][nt][1]);
            *(float2*)&C[(size_t)(r0 + 8) * NOUT + c] = make_float2(acc[mt][nt][2], acc[mt][nt][3]);
        }
    }
}

// =====================================================================
extern "C" void kernel_launch(void* const* d_in, const int* in_sizes, int n_in,
                              void* d_out, int out_size)
{
    const float* x      = (const float*)d_in[0];   // [8192, 512]
    const float* weight = (const float*)d_in[1];   // [64,64,8,8]
    const float* embed  = (const float*)d_in[2];   // [64,512]
    const int*   use_qw = (n_in >= 4) ? (const int*)d_in[3] : nullptr;
    float* out = (float*)d_out;

    vq_kernel<<<GROUPS / VQ_ROWS, 512>>>(weight, embed);
    convert_b<<<NOUT, 256>>>(embed, weight, use_qw, out, out_size);
    convert_a<<<BROWS, 256>>>(x);
    gemm_mma<<<dim3(NOUT / GBN, BROWS / GBM), 128>>>(out);
}

// round 13
// speedup vs baseline: 1.3468x; 1.3189x over previous
#include <cuda_runtime.h>
#include <cuda_fp16.h>
#include <cstdint>

typedef unsigned long long ull;

#define BROWS 8192
#define NOUT  512
#define NKDIM 512
#define NCODE 512
#define GROUPS 4096
#define WDIM   64

#define KEFF  1024          // 2 fp16 precision segments * 512
#define GBM   128
#define GBN   128
#define GBK   32
#define KITERS (KEFF / GBK) // 32
#define ASTR  40            // padded f16 row stride (conflict-free ldmatrix)

// ---------------- device scratch ----------------
__device__ __half g_A2[BROWS * KEFF];   // 16.8 MB  [Ah | Al]
__device__ __half g_B2[NOUT * KEFF];    // 1.0 MB   [Bh | Bh]
__device__ int   g_idx[GROUPS];
__device__ float g_mind[GROUPS];

__device__ __forceinline__ uint32_t smem_u32(const void* p) {
    uint32_t a;
    asm("{ .reg .u64 t; cvta.to.shared.u64 t, %1; cvt.u32.u64 %0, t; }" : "=r"(a) : "l"(p));
    return a;
}
__device__ __forceinline__ void cp16(uint32_t dst, const void* src) {
    asm volatile("cp.async.cg.shared.global [%0], [%1], 16;" :: "r"(dst), "l"(src));
}
#define CP_COMMIT() asm volatile("cp.async.commit_group;" ::: "memory")
#define CP_WAIT0()  asm volatile("cp.async.wait_group 0;" ::: "memory")

__device__ __forceinline__ void ldm_x4(uint32_t addr, uint32_t& r0, uint32_t& r1,
                                       uint32_t& r2, uint32_t& r3) {
    asm volatile("ldmatrix.sync.aligned.m8n8.x4.shared.b16 {%0,%1,%2,%3}, [%4];"
                 : "=r"(r0), "=r"(r1), "=r"(r2), "=r"(r3) : "r"(addr));
}
__device__ __forceinline__ void mma_f16(float* d, const uint32_t* a, const uint32_t* b) {
    asm volatile(
        "mma.sync.aligned.m16n8k16.row.col.f32.f16.f16.f32 "
        "{%0,%1,%2,%3}, {%4,%5,%6,%7}, {%8,%9}, {%0,%1,%2,%3};"
        : "+f"(d[0]), "+f"(d[1]), "+f"(d[2]), "+f"(d[3])
        : "r"(a[0]), "r"(a[1]), "r"(a[2]), "r"(a[3]), "r"(b[0]), "r"(b[1]));
}

// =====================================================================
// Kernel 1: VQ quantize (verified R5/R7)
// =====================================================================
#define VQ_ROWS 16

__global__ __launch_bounds__(512) void vq_kernel(
    const float* __restrict__ weight, const float* __restrict__ embed)
{
    __shared__ float w_s[VQ_ROWS][WDIM];
    __shared__ float wn_s[VQ_ROWS];
    __shared__ float dist_s[VQ_ROWS][NCODE];

    const int tid = threadIdx.x;
    const int r0  = blockIdx.x * VQ_ROWS;

    for (int t = tid; t < VQ_ROWS * WDIM; t += 512)
        w_s[t / WDIM][t % WDIM] = weight[r0 * WDIM + t];
    __syncthreads();

    if (tid < VQ_ROWS) {
        float s = 0.f;
#pragma unroll
        for (int k = 0; k < WDIM; k++) { float v = w_s[tid][k]; s += v * v; }
        wn_s[tid] = s;
    }

    float acc[VQ_ROWS];
#pragma unroll
    for (int r = 0; r < VQ_ROWS; r++) acc[r] = 0.f;
    float en = 0.f;
    const int j = tid;
#pragma unroll 4
    for (int k = 0; k < WDIM; k++) {
        float e = embed[k * NCODE + j];
        en += e * e;
#pragma unroll
        for (int r = 0; r < VQ_ROWS; r++) acc[r] += w_s[r][k] * e;
    }
#pragma unroll
    for (int r = 0; r < VQ_ROWS; r++) dist_s[r][j] = en - 2.f * acc[r];
    __syncthreads();

    const int warp = tid >> 5, lane = tid & 31;
    float best = 3.4e38f; int bi = 0;
    for (int c = lane; c < NCODE; c += 32) {
        float v = dist_s[warp][c];
        if (v < best) { best = v; bi = c; }
    }
#pragma unroll
    for (int off = 16; off > 0; off >>= 1) {
        float ov = __shfl_down_sync(0xffffffffu, best, off);
        int   oi = __shfl_down_sync(0xffffffffu, bi,   off);
        if (ov < best) { best = ov; bi = oi; }
    }
    if (lane == 0) {
        g_idx[r0 + warp]  = bi;
        g_mind[r0 + warp] = wn_s[warp] + best;
    }
}

// =====================================================================
// Kernel 2: x -> A2 fp16 [8192][1024], segments [Ah | Al]
// =====================================================================
__global__ __launch_bounds__(256) void convert_a(const float* __restrict__ x)
{
    const int t = blockIdx.x * 256 + threadIdx.x;
    const int m = t >> 8;
    const int k = (t & 255) * 2;

    const float2 v = *(const float2*)&x[m * NKDIM + k];
    __half2 hi = __float22half2_rn(v);
    float2 hf = __half22float2(hi);
    __half2 lo = __float22half2_rn(make_float2(v.x - hf.x, v.y - hf.y));

    __half* row = g_A2 + (size_t)m * KEFF;
    *(__half2*)&row[k]       = hi;
    *(__half2*)&row[512 + k] = lo;
}

// =====================================================================
// Kernel 3: W_eff^T -> B2 fp16 [512 n][1024 k], segments [Bh | Bh].
// Block 0 folds the deterministic diff reduction (verified R7).
// =====================================================================
__global__ __launch_bounds__(256) void convert_b(
    const float* __restrict__ embed, const float* __restrict__ weight,
    const int* __restrict__ use_qw_p, float* __restrict__ out, int out_size)
{
    const int n = blockIdx.x;          // 0..511
    const int k = threadIdx.x * 2;     // even k
    const int g = k >> 3, i0 = k & 7;
    const int og = n >> 3, om = n & 7;
    const int uq = use_qw_p ? *use_qw_p : 1;

    float v0, v1;
    if (uq) {
        const int ix = g_idx[g * 64 + og];
        v0 = embed[(i0 * 8 + om) * NCODE + ix];
        v1 = embed[((i0 + 1) * 8 + om) * NCODE + ix];
    } else {
        v0 = weight[(g * 64 + og) * WDIM + i0 * 8 + om];
        v1 = weight[(g * 64 + og) * WDIM + (i0 + 1) * 8 + om];
    }
    __half2 hi = __float22half2_rn(make_float2(v0, v1));

    __half* row = g_B2 + (size_t)n * KEFF;
    *(__half2*)&row[k]       = hi;
    *(__half2*)&row[512 + k] = hi;

    if (blockIdx.x == 0) {
        __shared__ float s[256];
        float a = 0.f;
        for (int i = threadIdx.x; i < GROUPS; i += 256) a += g_mind[i];
        s[threadIdx.x] = a;
        __syncthreads();
        for (int st = 128; st > 0; st >>= 1) {
            if (threadIdx.x < st) s[threadIdx.x] += s[threadIdx.x + st];
            __syncthreads();
        }
        if (threadIdx.x == 0 && out_size > BROWS * NOUT)
            out[BROWS * NOUT] = uq ? (s[0] / (float)(GROUPS * WDIM)) : 0.f;
    }
}

// =====================================================================
// Kernel 4: fp16 mma.sync GEMM — structure byte-identical to verified
// R5/R7 winner (128x128 tile, 256 thr, 8 warps 4m x 2n, BK=32, 2-stage
// static-smem cp.async pipeline). Only dtype + KITERS changed.
// =====================================================================
__global__ __launch_bounds__(256, 2) void gemm_mma(float* __restrict__ C)
{
    __shared__ __half As[2][GBM][ASTR];  // 20 KB
    __shared__ __half Bs[2][GBN][ASTR];  // 20 KB

    const int tid  = threadIdx.x;
    const int lane = tid & 31;
    const int wid  = tid >> 5;
    const int wm   = wid & 3;
    const int wn   = wid >> 2;

    const int m0 = blockIdx.y * GBM;
    const int n0 = blockIdx.x * GBN;

    const __half* Ag = g_A2 + (size_t)m0 * KEFF;
    const __half* Bg = g_B2 + (size_t)n0 * KEFF;

    const int c0_row = tid >> 2;
    const int c0_seg = tid & 3;
    const int c1_row = (tid + 256) >> 2;
    const int c1_seg = tid & 3;

    float acc[2][8][4];
#pragma unroll
    for (int mt = 0; mt < 2; mt++)
#pragma unroll
        for (int nt = 0; nt < 8; nt++)
#pragma unroll
            for (int q = 0; q < 4; q++) acc[mt][nt][q] = 0.f;

    auto load_stage = [&](int s, int kt) {
        cp16(smem_u32(&As[s][c0_row][c0_seg * 8]), Ag + (size_t)c0_row * KEFF + kt + c0_seg * 8);
        cp16(smem_u32(&As[s][c1_row][c1_seg * 8]), Ag + (size_t)c1_row * KEFF + kt + c1_seg * 8);
        cp16(smem_u32(&Bs[s][c0_row][c0_seg * 8]), Bg + (size_t)c0_row * KEFF + kt + c0_seg * 8);
        cp16(smem_u32(&Bs[s][c1_row][c1_seg * 8]), Bg + (size_t)c1_row * KEFF + kt + c1_seg * 8);
    };

    load_stage(0, 0);
    CP_COMMIT();

    for (int it = 0; it < KITERS; it++) {
        CP_WAIT0();
        __syncthreads();
        if (it + 1 < KITERS) {
            load_stage((it + 1) & 1, (it + 1) * GBK);
            CP_COMMIT();
        }
        const int s = it & 1;

        const uint32_t a_lane0 = smem_u32(&As[s][0][0]) +
            ((wm * 32 + (lane & 15)) * ASTR + (lane >> 4) * 8) * 2;
        const int bq = lane >> 3, br = lane & 7;
        const uint32_t b_lane0 = smem_u32(&Bs[s][0][0]) +
            ((wn * 64 + (bq >> 1) * 8 + br) * ASTR + (bq & 1) * 8) * 2;

#pragma unroll
        for (int ks = 0; ks < 2; ks++) {
            uint32_t a[2][4], b[8][2];
#pragma unroll
            for (int mt = 0; mt < 2; mt++)
                ldm_x4(a_lane0 + (mt * 16 * ASTR + ks * 16) * 2,
                       a[mt][0], a[mt][1], a[mt][2], a[mt][3]);
#pragma unroll
            for (int np = 0; np < 4; np++)
                ldm_x4(b_lane0 + (np * 16 * ASTR + ks * 16) * 2,
                       b[np * 2][0], b[np * 2][1], b[np * 2 + 1][0], b[np * 2 + 1][1]);
#pragma unroll
            for (int mt = 0; mt < 2; mt++)
#pragma unroll
                for (int nt = 0; nt < 8; nt++)
                    mma_f16(acc[mt][nt], a[mt], b[nt]);
        }
    }

    // Epilogue (fragment layout identical to verified kernels)
#pragma unroll
    for (int mt = 0; mt < 2; mt++) {
        const int r0 = m0 + wm * 32 + mt * 16 + (lane >> 2);
#pragma unroll
        for (int nt = 0; nt < 8; nt++) {
            const int c = n0 + wn * 64 + nt * 8 + (lane & 3) * 2;
            *(float2*)&C[(size_t)r0 * NOUT + c]       = make_float2(acc[mt][nt][0], acc[mt][nt][1]);
            *(float2*)&C[(size_t)(r0 + 8) * NOUT + c] = make_float2(acc[mt][nt][2], acc[mt][nt][3]);
        }
    }
}

// =====================================================================
extern "C" void kernel_launch(void* const* d_in, const int* in_sizes, int n_in,
                              void* d_out, int out_size)
{
    const float* x      = (const float*)d_in[0];   // [8192, 512]
    const float* weight = (const float*)d_in[1];   // [64,64,8,8]
    const float* embed  = (const float*)d_in[2];   // [64,512]
    const int*   use_qw = (n_in >= 4) ? (const int*)d_in[3] : nullptr;
    float* out = (float*)d_out;

    vq_kernel<<<GROUPS / VQ_ROWS, 512>>>(weight, embed);
    convert_b<<<NOUT, 256>>>(embed, weight, use_qw, out, out_size);
    convert_a<<<BROWS, 256>>>(x);
    gemm_mma<<<dim3(NOUT / GBN, BROWS / GBM), 256>>>(out);
}

// round 14
// speedup vs baseline: 1.4439x; 1.0721x over previous
#include <cuda_runtime.h>
#include <cuda_fp16.h>
#include <cstdint>

typedef unsigned long long ull;

#define BROWS 8192
#define NOUT  512
#define NKDIM 512
#define NCODE 512
#define GROUPS 4096
#define WDIM   64

#define KEFF  1024          // 2 fp16 precision segments * 512
#define GBM   128
#define GBN   128
#define GBK   32
#define KITERS (KEFF / GBK) // 32
#define ASTR  40            // padded f16 row stride (conflict-free ldmatrix)
#define NSTAGE 3
#define SMEM_BYTES (NSTAGE * (GBM + GBN) * ASTR * 2)   // 61440

// ---------------- device scratch ----------------
__device__ __half g_A2[BROWS * KEFF];   // 16.8 MB  [Ah | Al]
__device__ __half g_B2[NOUT * KEFF];    // 1.0 MB   [Bh | Bh]
__device__ int   g_idx[GROUPS];
__device__ float g_mind[GROUPS];

__device__ __forceinline__ uint32_t smem_u32(const void* p) {
    uint32_t a;
    asm("{ .reg .u64 t; cvta.to.shared.u64 t, %1; cvt.u32.u64 %0, t; }" : "=r"(a) : "l"(p));
    return a;
}
__device__ __forceinline__ void cp16(uint32_t dst, const void* src) {
    asm volatile("cp.async.cg.shared.global [%0], [%1], 16;" :: "r"(dst), "l"(src));
}
#define CP_COMMIT() asm volatile("cp.async.commit_group;" ::: "memory")
#define CP_WAIT0()  asm volatile("cp.async.wait_group 0;" ::: "memory")
#define CP_WAIT1()  asm volatile("cp.async.wait_group 1;" ::: "memory")

__device__ __forceinline__ void ldm_x4(uint32_t addr, uint32_t& r0, uint32_t& r1,
                                       uint32_t& r2, uint32_t& r3) {
    asm volatile("ldmatrix.sync.aligned.m8n8.x4.shared.b16 {%0,%1,%2,%3}, [%4];"
                 : "=r"(r0), "=r"(r1), "=r"(r2), "=r"(r3) : "r"(addr));
}
__device__ __forceinline__ void mma_f16(float* d, const uint32_t* a, const uint32_t* b) {
    asm volatile(
        "mma.sync.aligned.m16n8k16.row.col.f32.f16.f16.f32 "
        "{%0,%1,%2,%3}, {%4,%5,%6,%7}, {%8,%9}, {%0,%1,%2,%3};"
        : "+f"(d[0]), "+f"(d[1]), "+f"(d[2]), "+f"(d[3])
        : "r"(a[0]), "r"(a[1]), "r"(a[2]), "r"(a[3]), "r"(b[0]), "r"(b[1]));
}

// =====================================================================
// Kernel 1: VQ quantize (verified R5/R7/R12)
// =====================================================================
#define VQ_ROWS 16

__global__ __launch_bounds__(512) void vq_kernel(
    const float* __restrict__ weight, const float* __restrict__ embed)
{
    __shared__ float w_s[VQ_ROWS][WDIM];
    __shared__ float wn_s[VQ_ROWS];
    __shared__ float dist_s[VQ_ROWS][NCODE];

    const int tid = threadIdx.x;
    const int r0  = blockIdx.x * VQ_ROWS;

    for (int t = tid; t < VQ_ROWS * WDIM; t += 512)
        w_s[t / WDIM][t % WDIM] = weight[r0 * WDIM + t];
    __syncthreads();

    if (tid < VQ_ROWS) {
        float s = 0.f;
#pragma unroll
        for (int k = 0; k < WDIM; k++) { float v = w_s[tid][k]; s += v * v; }
        wn_s[tid] = s;
    }

    float acc[VQ_ROWS];
#pragma unroll
    for (int r = 0; r < VQ_ROWS; r++) acc[r] = 0.f;
    float en = 0.f;
    const int j = tid;
#pragma unroll 4
    for (int k = 0; k < WDIM; k++) {
        float e = embed[k * NCODE + j];
        en += e * e;
#pragma unroll
        for (int r = 0; r < VQ_ROWS; r++) acc[r] += w_s[r][k] * e;
    }
#pragma unroll
    for (int r = 0; r < VQ_ROWS; r++) dist_s[r][j] = en - 2.f * acc[r];
    __syncthreads();

    const int warp = tid >> 5, lane = tid & 31;
    float best = 3.4e38f; int bi = 0;
    for (int c = lane; c < NCODE; c += 32) {
        float v = dist_s[warp][c];
        if (v < best) { best = v; bi = c; }
    }
#pragma unroll
    for (int off = 16; off > 0; off >>= 1) {
        float ov = __shfl_down_sync(0xffffffffu, best, off);
        int   oi = __shfl_down_sync(0xffffffffu, bi,   off);
        if (ov < best) { best = ov; bi = oi; }
    }
    if (lane == 0) {
        g_idx[r0 + warp]  = bi;
        g_mind[r0 + warp] = wn_s[warp] + best;
    }
}

// =====================================================================
// Kernel 2: MERGED converts. Blocks 0..511: B2 build + diff fold
// (verified R12 conv_b math). Blocks 512..8703: A2 convert
// (verified R12 conv_a math, block = row). Both parts lightweight.
// =====================================================================
#define CB_BLOCKS NOUT          // 512
#define MERGED_BLOCKS (CB_BLOCKS + BROWS)

__global__ __launch_bounds__(256) void convert_ab(
    const float* __restrict__ x,
    const float* __restrict__ embed, const float* __restrict__ weight,
    const int* __restrict__ use_qw_p, float* __restrict__ out, int out_size)
{
    if (blockIdx.x >= CB_BLOCKS) {
        // ---------- convert_a part ----------
        const int m = blockIdx.x - CB_BLOCKS;
        const int k = threadIdx.x * 2;

        const float2 v = *(const float2*)&x[m * NKDIM + k];
        __half2 hi = __float22half2_rn(v);
        float2 hf = __half22float2(hi);
        __half2 lo = __float22half2_rn(make_float2(v.x - hf.x, v.y - hf.y));

        __half* row = g_A2 + (size_t)m * KEFF;
        *(__half2*)&row[k]       = hi;
        *(__half2*)&row[512 + k] = lo;
        return;
    }

    // ---------- convert_b part ----------
    const int n = blockIdx.x;          // 0..511
    const int k = threadIdx.x * 2;     // even k
    const int g = k >> 3, i0 = k & 7;
    const int og = n >> 3, om = n & 7;
    const int uq = use_qw_p ? *use_qw_p : 1;

    float v0, v1;
    if (uq) {
        const int ix = g_idx[g * 64 + og];
        v0 = embed[(i0 * 8 + om) * NCODE + ix];
        v1 = embed[((i0 + 1) * 8 + om) * NCODE + ix];
    } else {
        v0 = weight[(g * 64 + og) * WDIM + i0 * 8 + om];
        v1 = weight[(g * 64 + og) * WDIM + (i0 + 1) * 8 + om];
    }
    __half2 hi = __float22half2_rn(make_float2(v0, v1));

    __half* row = g_B2 + (size_t)n * KEFF;
    *(__half2*)&row[k]       = hi;
    *(__half2*)&row[512 + k] = hi;

    if (blockIdx.x == 0) {
        __shared__ float s[256];
        float a = 0.f;
        for (int i = threadIdx.x; i < GROUPS; i += 256) a += g_mind[i];
        s[threadIdx.x] = a;
        __syncthreads();
        for (int st = 128; st > 0; st >>= 1) {
            if (threadIdx.x < st) s[threadIdx.x] += s[threadIdx.x + st];
            __syncthreads();
        }
        if (threadIdx.x == 0 && out_size > BROWS * NOUT)
            out[BROWS * NOUT] = uq ? (s[0] / (float)(GROUPS * WDIM)) : 0.f;
    }
}

// =====================================================================
// Kernel 3: fp16 mma.sync GEMM. Identical math/layout to verified R12;
// ONLY change: 2-stage/wait0 -> 3-stage/wait1 pipeline (dynamic smem).
// =====================================================================
__global__ __launch_bounds__(256, 2) void gemm_mma(float* __restrict__ C)
{
    extern __shared__ __half sh[];
    __half* const AsBase = sh;                        // [NSTAGE][GBM][ASTR]
    __half* const BsBase = sh + NSTAGE * GBM * ASTR;  // [NSTAGE][GBN][ASTR]

    const int tid  = threadIdx.x;
    const int lane = tid & 31;
    const int wid  = tid >> 5;
    const int wm   = wid & 3;
    const int wn   = wid >> 2;

    const int m0 = blockIdx.y * GBM;
    const int n0 = blockIdx.x * GBN;

    const __half* Ag = g_A2 + (size_t)m0 * KEFF;
    const __half* Bg = g_B2 + (size_t)n0 * KEFF;

    const int c0_row = tid >> 2;
    const int c0_seg = tid & 3;
    const int c1_row = (tid + 256) >> 2;
    const int c1_seg = tid & 3;

    float acc[2][8][4];
#pragma unroll
    for (int mt = 0; mt < 2; mt++)
#pragma unroll
        for (int nt = 0; nt < 8; nt++)
#pragma unroll
            for (int q = 0; q < 4; q++) acc[mt][nt][q] = 0.f;

    auto load_stage = [&](int s, int kt) {
        __half* As = AsBase + s * (GBM * ASTR);
        __half* Bs = BsBase + s * (GBN * ASTR);
        cp16(smem_u32(&As[c0_row * ASTR + c0_seg * 8]), Ag + (size_t)c0_row * KEFF + kt + c0_seg * 8);
        cp16(smem_u32(&As[c1_row * ASTR + c1_seg * 8]), Ag + (size_t)c1_row * KEFF + kt + c1_seg * 8);
        cp16(smem_u32(&Bs[c0_row * ASTR + c0_seg * 8]), Bg + (size_t)c0_row * KEFF + kt + c0_seg * 8);
        cp16(smem_u32(&Bs[c1_row * ASTR + c1_seg * 8]), Bg + (size_t)c1_row * KEFF + kt + c1_seg * 8);
    };

    load_stage(0, 0); CP_COMMIT();
    load_stage(1, GBK); CP_COMMIT();

    int s = 0;
    for (int it = 0; it < KITERS; it++) {
        if (it + 1 < KITERS) { CP_WAIT1(); } else { CP_WAIT0(); }
        __syncthreads();
        if (it + 2 < KITERS) {
            int sn = s + 2; if (sn >= NSTAGE) sn -= NSTAGE;
            load_stage(sn, (it + 2) * GBK);
            CP_COMMIT();
        }

        const __half* As = AsBase + s * (GBM * ASTR);
        const __half* Bs = BsBase + s * (GBN * ASTR);
        const uint32_t a_lane0 = smem_u32(As) +
            ((wm * 32 + (lane & 15)) * ASTR + (lane >> 4) * 8) * 2;
        const int bq = lane >> 3, br = lane & 7;
        const uint32_t b_lane0 = smem_u32(Bs) +
            ((wn * 64 + (bq >> 1) * 8 + br) * ASTR + (bq & 1) * 8) * 2;

#pragma unroll
        for (int ks = 0; ks < 2; ks++) {
            uint32_t a[2][4], b[8][2];
#pragma unroll
            for (int mt = 0; mt < 2; mt++)
                ldm_x4(a_lane0 + (mt * 16 * ASTR + ks * 16) * 2,
                       a[mt][0], a[mt][1], a[mt][2], a[mt][3]);
#pragma unroll
            for (int np = 0; np < 4; np++)
                ldm_x4(b_lane0 + (np * 16 * ASTR + ks * 16) * 2,
                       b[np * 2][0], b[np * 2][1], b[np * 2 + 1][0], b[np * 2 + 1][1]);
#pragma unroll
            for (int mt = 0; mt < 2; mt++)
#pragma unroll
                for (int nt = 0; nt < 8; nt++)
                    mma_f16(acc[mt][nt], a[mt], b[nt]);
        }

        if (++s >= NSTAGE) s = 0;
    }

    // Epilogue (fragment layout identical to verified kernels)
#pragma unroll
    for (int mt = 0; mt < 2; mt++) {
        const int r0 = m0 + wm * 32 + mt * 16 + (lane >> 2);
#pragma unroll
        for (int nt = 0; nt < 8; nt++) {
            const int c = n0 + wn * 64 + nt * 8 + (lane & 3) * 2;
            *(float2*)&C[(size_t)r0 * NOUT + c]       = make_float2(acc[mt][nt][0], acc[mt][nt][1]);
            *(float2*)&C[(size_t)(r0 + 8) * NOUT + c] = make_float2(acc[mt][nt][2], acc[mt][nt][3]);
        }
    }
}

// =====================================================================
extern "C" void kernel_launch(void* const* d_in, const int* in_sizes, int n_in,
                              void* d_out, int out_size)
{
    const float* x      = (const float*)d_in[0];   // [8192, 512]
    const float* weight = (const float*)d_in[1];   // [64,64,8,8]
    const float* embed  = (const float*)d_in[2];   // [64,512]
    const int*   use_qw = (n_in >= 4) ? (const int*)d_in[3] : nullptr;
    float* out = (float*)d_out;

    cudaFuncSetAttribute(gemm_mma, cudaFuncAttributeMaxDynamicSharedMemorySize,
                         SMEM_BYTES);

    vq_kernel<<<GROUPS / VQ_ROWS, 512>>>(weight, embed);
    convert_ab<<<MERGED_BLOCKS, 256>>>(x, embed, weight, use_qw, out, out_size);
    gemm_mma<<<dim3(NOUT / GBN, BROWS / GBM), 256, SMEM_BYTES>>>(out);
}

// round 15
// speedup vs baseline: 1.4950x; 1.0354x over previous
#include <cuda_runtime.h>
#include <cuda_fp16.h>
#include <cstdint>

typedef unsigned long long ull;

#define BROWS 8192
#define NOUT  512
#define NKDIM 512
#define NCODE 512
#define GROUPS 4096
#define WDIM   64

#define KEFF  1024          // 2 fp16 precision segments * 512
#define GBM   128
#define GBN   128
#define GBK   32
#define KITERS (KEFF / GBK) // 32
#define ASTR  40            // padded f16 row stride (conflict-free ldmatrix)
#define NSTAGE 3
#define SMEM_BYTES (NSTAGE * (GBM + GBN) * ASTR * 2)   // 61440

// ---------------- device scratch ----------------
__device__ __half g_A2[BROWS * KEFF];   // 16.8 MB  [Ah | Al]
__device__ __half g_B2[NOUT * KEFF];    // 1.0 MB   [Bh | Bh]
__device__ int   g_idx[GROUPS];
__device__ float g_mind[GROUPS];

__device__ __forceinline__ uint32_t smem_u32(const void* p) {
    uint32_t a;
    asm("{ .reg .u64 t; cvta.to.shared.u64 t, %1; cvt.u32.u64 %0, t; }" : "=r"(a) : "l"(p));
    return a;
}
__device__ __forceinline__ void cp16(uint32_t dst, const void* src) {
    asm volatile("cp.async.cg.shared.global [%0], [%1], 16;" :: "r"(dst), "l"(src));
}
#define CP_COMMIT() asm volatile("cp.async.commit_group;" ::: "memory")
#define CP_WAIT0()  asm volatile("cp.async.wait_group 0;" ::: "memory")
#define CP_WAIT1()  asm volatile("cp.async.wait_group 1;" ::: "memory")

__device__ __forceinline__ void ldm_x4(uint32_t addr, uint32_t& r0, uint32_t& r1,
                                       uint32_t& r2, uint32_t& r3) {
    asm volatile("ldmatrix.sync.aligned.m8n8.x4.shared.b16 {%0,%1,%2,%3}, [%4];"
                 : "=r"(r0), "=r"(r1), "=r"(r2), "=r"(r3) : "r"(addr));
}
__device__ __forceinline__ void mma_f16(float* d, const uint32_t* a, const uint32_t* b) {
    asm volatile(
        "mma.sync.aligned.m16n8k16.row.col.f32.f16.f16.f32 "
        "{%0,%1,%2,%3}, {%4,%5,%6,%7}, {%8,%9}, {%0,%1,%2,%3};"
        : "+f"(d[0]), "+f"(d[1]), "+f"(d[2]), "+f"(d[3])
        : "r"(a[0]), "r"(a[1]), "r"(a[2]), "r"(a[3]), "r"(b[0]), "r"(b[1]));
}

// =====================================================================
// Kernel 1: VQ quantize. Same exact math as verified R13, but
// VQ_ROWS 16 -> 8: acc[8] halves reg pressure (76 -> ~40 regs),
// 3 CTAs/SM instead of 1, grid 256 -> 512 for balanced waves.
// =====================================================================
#define VQ_ROWS 8

__global__ __launch_bounds__(512) void vq_kernel(
    const float* __restrict__ weight, const float* __restrict__ embed)
{
    __shared__ float w_s[VQ_ROWS][WDIM];
    __shared__ float wn_s[VQ_ROWS];
    __shared__ float dist_s[VQ_ROWS][NCODE];

    const int tid = threadIdx.x;
    const int r0  = blockIdx.x * VQ_ROWS;

    for (int t = tid; t < VQ_ROWS * WDIM; t += 512)
        w_s[t / WDIM][t % WDIM] = weight[r0 * WDIM + t];
    __syncthreads();

    if (tid < VQ_ROWS) {
        float s = 0.f;
#pragma unroll
        for (int k = 0; k < WDIM; k++) { float v = w_s[tid][k]; s += v * v; }
        wn_s[tid] = s;
    }

    float acc[VQ_ROWS];
#pragma unroll
    for (int r = 0; r < VQ_ROWS; r++) acc[r] = 0.f;
    float en = 0.f;
    const int j = tid;
#pragma unroll 4
    for (int k = 0; k < WDIM; k++) {
        float e = embed[k * NCODE + j];
        en += e * e;
#pragma unroll
        for (int r = 0; r < VQ_ROWS; r++) acc[r] += w_s[r][k] * e;
    }
#pragma unroll
    for (int r = 0; r < VQ_ROWS; r++) dist_s[r][j] = en - 2.f * acc[r];
    __syncthreads();

    const int warp = tid >> 5, lane = tid & 31;
    if (warp < VQ_ROWS) {
        float best = 3.4e38f; int bi = 0;
        for (int c = lane; c < NCODE; c += 32) {
            float v = dist_s[warp][c];
            if (v < best) { best = v; bi = c; }
        }
#pragma unroll
        for (int off = 16; off > 0; off >>= 1) {
            float ov = __shfl_down_sync(0xffffffffu, best, off);
            int   oi = __shfl_down_sync(0xffffffffu, bi,   off);
            if (ov < best) { best = ov; bi = oi; }
        }
        if (lane == 0) {
            g_idx[r0 + warp]  = bi;
            g_mind[r0 + warp] = wn_s[warp] + best;
        }
    }
}

// =====================================================================
// Kernel 2: MERGED converts (verified R13). Blocks 0..511: B2 + diff
// fold. Blocks 512..8703: A2 convert.
// =====================================================================
#define CB_BLOCKS NOUT          // 512
#define MERGED_BLOCKS (CB_BLOCKS + BROWS)

__global__ __launch_bounds__(256) void convert_ab(
    const float* __restrict__ x,
    const float* __restrict__ embed, const float* __restrict__ weight,
    const int* __restrict__ use_qw_p, float* __restrict__ out, int out_size)
{
    if (blockIdx.x >= CB_BLOCKS) {
        const int m = blockIdx.x - CB_BLOCKS;
        const int k = threadIdx.x * 2;

        const float2 v = *(const float2*)&x[m * NKDIM + k];
        __half2 hi = __float22half2_rn(v);
        float2 hf = __half22float2(hi);
        __half2 lo = __float22half2_rn(make_float2(v.x - hf.x, v.y - hf.y));

        __half* row = g_A2 + (size_t)m * KEFF;
        *(__half2*)&row[k]       = hi;
        *(__half2*)&row[512 + k] = lo;
        return;
    }

    const int n = blockIdx.x;          // 0..511
    const int k = threadIdx.x * 2;     // even k
    const int g = k >> 3, i0 = k & 7;
    const int og = n >> 3, om = n & 7;
    const int uq = use_qw_p ? *use_qw_p : 1;

    float v0, v1;
    if (uq) {
        const int ix = g_idx[g * 64 + og];
        v0 = embed[(i0 * 8 + om) * NCODE + ix];
        v1 = embed[((i0 + 1) * 8 + om) * NCODE + ix];
    } else {
        v0 = weight[(g * 64 + og) * WDIM + i0 * 8 + om];
        v1 = weight[(g * 64 + og) * WDIM + (i0 + 1) * 8 + om];
    }
    __half2 hi = __float22half2_rn(make_float2(v0, v1));

    __half* row = g_B2 + (size_t)n * KEFF;
    *(__half2*)&row[k]       = hi;
    *(__half2*)&row[512 + k] = hi;

    if (blockIdx.x == 0) {
        __shared__ float s[256];
        float a = 0.f;
        for (int i = threadIdx.x; i < GROUPS; i += 256) a += g_mind[i];
        s[threadIdx.x] = a;
        __syncthreads();
        for (int st = 128; st > 0; st >>= 1) {
            if (threadIdx.x < st) s[threadIdx.x] += s[threadIdx.x + st];
            __syncthreads();
        }
        if (threadIdx.x == 0 && out_size > BROWS * NOUT)
            out[BROWS * NOUT] = uq ? (s[0] / (float)(GROUPS * WDIM)) : 0.f;
    }
}

// =====================================================================
// Kernel 3: fp16 mma.sync GEMM, 3-stage pipeline (verified R13).
// =====================================================================
__global__ __launch_bounds__(256, 2) void gemm_mma(float* __restrict__ C)
{
    extern __shared__ __half sh[];
    __half* const AsBase = sh;                        // [NSTAGE][GBM][ASTR]
    __half* const BsBase = sh + NSTAGE * GBM * ASTR;  // [NSTAGE][GBN][ASTR]

    const int tid  = threadIdx.x;
    const int lane = tid & 31;
    const int wid  = tid >> 5;
    const int wm   = wid & 3;
    const int wn   = wid >> 2;

    const int m0 = blockIdx.y * GBM;
    const int n0 = blockIdx.x * GBN;

    const __half* Ag = g_A2 + (size_t)m0 * KEFF;
    const __half* Bg = g_B2 + (size_t)n0 * KEFF;

    const int c0_row = tid >> 2;
    const int c0_seg = tid & 3;
    const int c1_row = (tid + 256) >> 2;
    const int c1_seg = tid & 3;

    float acc[2][8][4];
#pragma unroll
    for (int mt = 0; mt < 2; mt++)
#pragma unroll
        for (int nt = 0; nt < 8; nt++)
#pragma unroll
            for (int q = 0; q < 4; q++) acc[mt][nt][q] = 0.f;

    auto load_stage = [&](int s, int kt) {
        __half* As = AsBase + s * (GBM * ASTR);
        __half* Bs = BsBase + s * (GBN * ASTR);
        cp16(smem_u32(&As[c0_row * ASTR + c0_seg * 8]), Ag + (size_t)c0_row * KEFF + kt + c0_seg * 8);
        cp16(smem_u32(&As[c1_row * ASTR + c1_seg * 8]), Ag + (size_t)c1_row * KEFF + kt + c1_seg * 8);
        cp16(smem_u32(&Bs[c0_row * ASTR + c0_seg * 8]), Bg + (size_t)c0_row * KEFF + kt + c0_seg * 8);
        cp16(smem_u32(&Bs[c1_row * ASTR + c1_seg * 8]), Bg + (size_t)c1_row * KEFF + kt + c1_seg * 8);
    };

    load_stage(0, 0); CP_COMMIT();
    load_stage(1, GBK); CP_COMMIT();

    int s = 0;
    for (int it = 0; it < KITERS; it++) {
        if (it + 1 < KITERS) { CP_WAIT1(); } else { CP_WAIT0(); }
        __syncthreads();
        if (it + 2 < KITERS) {
            int sn = s + 2; if (sn >= NSTAGE) sn -= NSTAGE;
            load_stage(sn, (it + 2) * GBK);
            CP_COMMIT();
        }

        const __half* As = AsBase + s * (GBM * ASTR);
        const __half* Bs = BsBase + s * (GBN * ASTR);
        const uint32_t a_lane0 = smem_u32(As) +
            ((wm * 32 + (lane & 15)) * ASTR + (lane >> 4) * 8) * 2;
        const int bq = lane >> 3, br = lane & 7;
        const uint32_t b_lane0 = smem_u32(Bs) +
            ((wn * 64 + (bq >> 1) * 8 + br) * ASTR + (bq & 1) * 8) * 2;

#pragma unroll
        for (int ks = 0; ks < 2; ks++) {
            uint32_t a[2][4], b[8][2];
#pragma unroll
            for (int mt = 0; mt < 2; mt++)
                ldm_x4(a_lane0 + (mt * 16 * ASTR + ks * 16) * 2,
                       a[mt][0], a[mt][1], a[mt][2], a[mt][3]);
#pragma unroll
            for (int np = 0; np < 4; np++)
                ldm_x4(b_lane0 + (np * 16 * ASTR + ks * 16) * 2,
                       b[np * 2][0], b[np * 2][1], b[np * 2 + 1][0], b[np * 2 + 1][1]);
#pragma unroll
            for (int mt = 0; mt < 2; mt++)
#pragma unroll
                for (int nt = 0; nt < 8; nt++)
                    mma_f16(acc[mt][nt], a[mt], b[nt]);
        }

        if (++s >= NSTAGE) s = 0;
    }

    // Epilogue
#pragma unroll
    for (int mt = 0; mt < 2; mt++) {
        const int r0 = m0 + wm * 32 + mt * 16 + (lane >> 2);
#pragma unroll
        for (int nt = 0; nt < 8; nt++) {
            const int c = n0 + wn * 64 + nt * 8 + (lane & 3) * 2;
            *(float2*)&C[(size_t)r0 * NOUT + c]       = make_float2(acc[mt][nt][0], acc[mt][nt][1]);
            *(float2*)&C[(size_t)(r0 + 8) * NOUT + c] = make_float2(acc[mt][nt][2], acc[mt][nt][3]);
        }
    }
}

// =====================================================================
extern "C" void kernel_launch(void* const* d_in, const int* in_sizes, int n_in,
                              void* d_out, int out_size)
{
    const float* x      = (const float*)d_in[0];   // [8192, 512]
    const float* weight = (const float*)d_in[1];   // [64,64,8,8]
    const float* embed  = (const float*)d_in[2];   // [64,512]
    const int*   use_qw = (n_in >= 4) ? (const int*)d_in[3] : nullptr;
    float* out = (float*)d_out;

    cudaFuncSetAttribute(gemm_mma, cudaFuncAttributeMaxDynamicSharedMemorySize,
                         SMEM_BYTES);

    vq_kernel<<<GROUPS / VQ_ROWS, 512>>>(weight, embed);
    convert_ab<<<MERGED_BLOCKS, 256>>>(x, embed, weight, use_qw, out, out_size);
    gemm_mma<<<dim3(NOUT / GBN, BROWS / GBM), 256, SMEM_BYTES>>>(out);
}